// round 2
// baseline (speedup 1.0000x reference)
#include <cuda_runtime.h>
#include <cuda_bf16.h>
#include <float.h>

// Problem constants
#define NROWS   262144      // 16*128*128
#define DIM     64
#define NCODES  512
#define NELEM   (NROWS * DIM)   // 16777216

// Tiling for the argmin GEMM
#define BM 128      // rows per block
#define BKT 128     // codes per k-tile (4 tiles cover 512)
#define DC 16       // d-chunk

// Scratch (device globals -- no allocation allowed)
__device__ int   g_code[NROWS];
__device__ float g_norms[NCODES];
__device__ float g_dictT[NCODES * DIM];   // [k][d] transposed codebook
__device__ float g_partials[4096];

// ---------------------------------------------------------------------------
// Init: codebook norms + transpose. dict is [D, K] (k fastest).
// ---------------------------------------------------------------------------
__global__ void init_kernel(const float* __restrict__ dict) {
    int k = threadIdx.x;   // 512 threads
    float s = 0.0f;
    #pragma unroll 8
    for (int d = 0; d < DIM; d++) {
        float v = dict[d * NCODES + k];   // coalesced across k
        s += v * v;
        g_dictT[k * DIM + d] = v;
    }
    g_norms[k] = s;
}

// ---------------------------------------------------------------------------
// Kernel A: per-row argmin over 512 codes.
// dist = (||f||^2 + ||d_k||^2) - 2*sim   (matches reference expression incl.
// the row-norm shift, so tie quantization matches the reference argmin).
// Block: 256 threads = 16x16; block tile 128 rows x 128 codes, 4 code tiles.
// ---------------------------------------------------------------------------
__global__ __launch_bounds__(256) void argmin_kernel(
    const float* __restrict__ x, const float* __restrict__ dict)
{
    __shared__ float xs[DC][BM];     // 8 KB (transposed x chunk)
    __shared__ float ws[DC][BKT];    // 8 KB (dict chunk)
    __shared__ float ns[NCODES];     // 2 KB
    __shared__ float redd[BM][16];   // 8 KB
    __shared__ int   redk[BM][16];   // 8 KB

    const int tid = threadIdx.x;
    const int tx = tid & 15;
    const int ty = tid >> 4;
    const long row0 = (long)blockIdx.x * BM;

    ns[tid]       = g_norms[tid];
    ns[tid + 256] = g_norms[tid + 256];

    float best[8];
    int   bestk[8];
    float rn[8];
    #pragma unroll
    for (int i = 0; i < 8; i++) { best[i] = FLT_MAX; bestk[i] = 0; rn[i] = 0.0f; }

    for (int kt = 0; kt < 4; kt++) {
        float acc[8][8];
        #pragma unroll
        for (int i = 0; i < 8; i++)
            #pragma unroll
            for (int j = 0; j < 8; j++) acc[i][j] = 0.0f;

        for (int dt = 0; dt < 4; dt++) {
            // load x chunk transposed: xs[dd][row]
            #pragma unroll
            for (int l = 0; l < 2; l++) {
                int i = tid + l * 256;          // 0..511 float4 slots
                int r = i >> 2, seg = i & 3;
                float4 v = *(const float4*)(x + (row0 + r) * DIM + dt * DC + seg * 4);
                xs[seg * 4 + 0][r] = v.x;
                xs[seg * 4 + 1][r] = v.y;
                xs[seg * 4 + 2][r] = v.z;
                xs[seg * 4 + 3][r] = v.w;
            }
            // load dict chunk: ws[dd][k]
            #pragma unroll
            for (int l = 0; l < 2; l++) {
                int i = tid + l * 256;
                int dd = i >> 5, kq = i & 31;
                *(float4*)&ws[dd][kq * 4] =
                    *(const float4*)(dict + (dt * DC + dd) * NCODES + kt * BKT + kq * 4);
            }
            __syncthreads();

            #pragma unroll
            for (int dd = 0; dd < DC; dd++) {
                float a[8], b[8];
                *(float4*)(a)     = *(const float4*)&xs[dd][ty * 8];
                *(float4*)(a + 4) = *(const float4*)&xs[dd][ty * 8 + 4];
                *(float4*)(b)     = *(const float4*)&ws[dd][tx * 8];
                *(float4*)(b + 4) = *(const float4*)&ws[dd][tx * 8 + 4];
                if (kt == 0) {
                    #pragma unroll
                    for (int i = 0; i < 8; i++) rn[i] += a[i] * a[i];
                }
                #pragma unroll
                for (int i = 0; i < 8; i++)
                    #pragma unroll
                    for (int j = 0; j < 8; j++)
                        acc[i][j] += a[i] * b[j];
            }
            __syncthreads();
        }

        // update running argmin (k ascending in loop order -> first-min ties)
        #pragma unroll
        for (int j = 0; j < 8; j++) {
            int k = kt * BKT + tx * 8 + j;
            float nk = ns[k];
            #pragma unroll
            for (int i = 0; i < 8; i++) {
                float t  = rn[i] + nk;         // (||f||^2 + ||d||^2)
                float dv = t - 2.0f * acc[i][j];
                if (dv < best[i]) { best[i] = dv; bestk[i] = k; }
            }
        }
    }

    // cross-thread reduction over the 16 code groups per row
    #pragma unroll
    for (int i = 0; i < 8; i++) {
        redd[ty * 8 + i][tx] = best[i];
        redk[ty * 8 + i][tx] = bestk[i];
    }
    __syncthreads();
    if (tid < BM) {
        float bd = redd[tid][0];
        int   bk = redk[tid][0];
        #pragma unroll
        for (int t = 1; t < 16; t++) {
            float dv = redd[tid][t];
            int   kk = redk[tid][t];
            if (dv < bd || (dv == bd && kk < bk)) { bd = dv; bk = kk; }
        }
        g_code[row0 + tid] = bk;
    }
}

// ---------------------------------------------------------------------------
// Kernel B: gather q, write q_st = x + (q - x), accumulate sum (x-q)^2
// ---------------------------------------------------------------------------
__global__ __launch_bounds__(256) void gather_kernel(
    const float* __restrict__ x, float* __restrict__ out)
{
    const int tid = threadIdx.x;
    float s = 0.0f;
    #pragma unroll
    for (int it = 0; it < 4; it++) {
        long idx4 = (long)blockIdx.x * 1024 + it * 256 + tid;  // float4 index
        long e0 = idx4 * 4;
        int row = (int)(e0 >> 6);
        int db  = (int)(e0 & 63);
        int k = g_code[row];
        float4 xv = ((const float4*)x)[idx4];
        float4 qv = *(const float4*)&g_dictT[k * DIM + db];
        float4 ov;
        ov.x = xv.x + (qv.x - xv.x);
        ov.y = xv.y + (qv.y - xv.y);
        ov.z = xv.z + (qv.z - xv.z);
        ov.w = xv.w + (qv.w - xv.w);
        ((float4*)out)[idx4] = ov;
        float d0 = xv.x - qv.x, d1 = xv.y - qv.y, d2 = xv.z - qv.z, d3 = xv.w - qv.w;
        s += d0 * d0 + d1 * d1 + d2 * d2 + d3 * d3;
    }
    // block reduction
    __shared__ float red[8];
    #pragma unroll
    for (int o = 16; o > 0; o >>= 1) s += __shfl_down_sync(0xffffffffu, s, o);
    int lane = tid & 31, wid = tid >> 5;
    if (lane == 0) red[wid] = s;
    __syncthreads();
    if (wid == 0) {
        float v = (lane < 8) ? red[lane] : 0.0f;
        #pragma unroll
        for (int o = 4; o > 0; o >>= 1) v += __shfl_down_sync(0xffffffffu, v, o);
        if (lane == 0) g_partials[blockIdx.x] = v;
    }
}

// ---------------------------------------------------------------------------
// Kernel C: final loss reduction
// ---------------------------------------------------------------------------
__global__ __launch_bounds__(512) void finalize_kernel(float* __restrict__ out, int out_size) {
    const int tid = threadIdx.x;
    float s = 0.0f;
    #pragma unroll
    for (int i = 0; i < 8; i++) s += g_partials[tid + i * 512];
    __shared__ float red[16];
    #pragma unroll
    for (int o = 16; o > 0; o >>= 1) s += __shfl_down_sync(0xffffffffu, s, o);
    int lane = tid & 31, wid = tid >> 5;
    if (lane == 0) red[wid] = s;
    __syncthreads();
    if (tid == 0) {
        float tot = 0.0f;
        #pragma unroll
        for (int w = 0; w < 16; w++) tot += red[w];
        float m = tot / (float)NELEM;
        if (out_size > NELEM) out[NELEM] = m + 0.25f * m;   // dict + BETA*commit
    }
}

extern "C" void kernel_launch(void* const* d_in, const int* in_sizes, int n_in,
                              void* d_out, int out_size) {
    const float* x    = (const float*)d_in[0];     // [16,128,128,64]
    const float* dict = (const float*)d_in[1];     // [64,512]
    float* out = (float*)d_out;

    init_kernel<<<1, 512>>>(dict);
    argmin_kernel<<<NROWS / BM, 256>>>(x, dict);
    gather_kernel<<<4096, 256>>>(x, out);
    finalize_kernel<<<1, 512>>>(out, out_size);
}

// round 3
// speedup vs baseline: 1.0656x; 1.0656x over previous
#include <cuda_runtime.h>
#include <cuda_bf16.h>
#include <float.h>

// Problem constants
#define NROWS   262144      // 16*128*128
#define DIM     64
#define NCODES  512
#define NELEM   (NROWS * DIM)   // 16777216

// Tiling
#define BM 128      // rows per block
#define BKT 128     // codes per k-tile (4 tiles cover 512)
#define DC 16       // d-chunk

typedef unsigned long long u64;

// packed fp32x2 FMA: acc.lo += a.lo*b.lo; acc.hi += a.hi*b.hi  (exact fp32 each)
#define FMA2(acc, a, b) \
    asm("fma.rn.f32x2 %0, %1, %2, %0;" : "+l"(acc) : "l"(a), "l"(b))
#define PACK2(out, v) \
    asm("mov.b64 %0, {%1, %1};" : "=l"(out) : "r"(__float_as_uint(v)))
#define UNPACK2(lo, hi, in) \
    asm("mov.b64 {%0, %1}, %2;" : "=r"(lo), "=r"(hi) : "l"(in))

// Scratch (device globals -- no allocation allowed)
__device__ float g_norms[NCODES];
__device__ float g_dictT[NCODES * DIM];   // [k][d] transposed codebook
__device__ float g_partials[2048];

// ---------------------------------------------------------------------------
// Init: codebook norms + transpose. dict is [D, K] (k fastest).
// ---------------------------------------------------------------------------
__global__ void init_kernel(const float* __restrict__ dict) {
    int k = threadIdx.x;   // 512 threads
    float s = 0.0f;
    #pragma unroll 8
    for (int d = 0; d < DIM; d++) {
        float v = dict[d * NCODES + k];   // coalesced across k
        s += v * v;
        g_dictT[k * DIM + d] = v;
    }
    g_norms[k] = s;
}

// ---------------------------------------------------------------------------
// Fused kernel: per-row argmin over 512 codes (FFMA2 GEMM), then gather q,
// write q_st = x + (q - x), accumulate per-block sum (x-q)^2.
// dist = (||f||^2 + ||d_k||^2) - 2*sim   (matches reference expression so
// tie quantization matches the reference argmin).
// Block: 256 threads = 16x16; block tile 128 rows x 128 codes, 4 code tiles.
// ---------------------------------------------------------------------------
__global__ __launch_bounds__(256) void argmin_fused_kernel(
    const float* __restrict__ x, const float* __restrict__ dict,
    float* __restrict__ out)
{
    __shared__ float xs[DC][BM];     // 8 KB (transposed x chunk)
    __shared__ float ws[DC][BKT];    // 8 KB (dict chunk)
    __shared__ float ns[NCODES];     // 2 KB
    __shared__ float redd[BM][16];   // 8 KB
    __shared__ int   redk[BM][16];   // 8 KB
    __shared__ int   codes_s[BM];

    const int tid = threadIdx.x;
    const int tx = tid & 15;
    const int ty = tid >> 4;
    const long row0 = (long)blockIdx.x * BM;

    ns[tid]       = g_norms[tid];
    ns[tid + 256] = g_norms[tid + 256];

    float best[8];
    int   bestk[8];
    float rn[8];
    #pragma unroll
    for (int i = 0; i < 8; i++) { best[i] = FLT_MAX; bestk[i] = 0; rn[i] = 0.0f; }

    for (int kt = 0; kt < 4; kt++) {
        u64 acc2[8][4];   // 8 rows x 4 code-pairs (packed fp32x2)
        #pragma unroll
        for (int i = 0; i < 8; i++)
            #pragma unroll
            for (int j = 0; j < 4; j++) acc2[i][j] = 0ULL;

        for (int dt = 0; dt < 4; dt++) {
            // load x chunk transposed: xs[dd][row]
            #pragma unroll
            for (int l = 0; l < 2; l++) {
                int i = tid + l * 256;          // 0..511 float4 slots
                int r = i >> 2, seg = i & 3;
                float4 v = *(const float4*)(x + (row0 + r) * DIM + dt * DC + seg * 4);
                xs[seg * 4 + 0][r] = v.x;
                xs[seg * 4 + 1][r] = v.y;
                xs[seg * 4 + 2][r] = v.z;
                xs[seg * 4 + 3][r] = v.w;
            }
            // load dict chunk: ws[dd][k]
            #pragma unroll
            for (int l = 0; l < 2; l++) {
                int i = tid + l * 256;
                int dd = i >> 5, kq = i & 31;
                *(float4*)&ws[dd][kq * 4] =
                    *(const float4*)(dict + (dt * DC + dd) * NCODES + kt * BKT + kq * 4);
            }
            __syncthreads();

            #pragma unroll
            for (int dd = 0; dd < DC; dd++) {
                float a[8];
                *(float4*)(a)     = *(const float4*)&xs[dd][ty * 8];
                *(float4*)(a + 4) = *(const float4*)&xs[dd][ty * 8 + 4];
                // b: 8 adjacent floats = 4 packed f32x2 (16B-aligned loads)
                u64 bb[4];
                {
                    ulonglong2 b01 = *(const ulonglong2*)&ws[dd][tx * 8];
                    ulonglong2 b23 = *(const ulonglong2*)&ws[dd][tx * 8 + 4];
                    bb[0] = b01.x; bb[1] = b01.y; bb[2] = b23.x; bb[3] = b23.y;
                }
                if (kt == 0) {
                    #pragma unroll
                    for (int i = 0; i < 8; i++) rn[i] = fmaf(a[i], a[i], rn[i]);
                }
                #pragma unroll
                for (int i = 0; i < 8; i++) {
                    u64 aa;
                    PACK2(aa, a[i]);
                    #pragma unroll
                    for (int j = 0; j < 4; j++)
                        FMA2(acc2[i][j], aa, bb[j]);
                }
            }
            __syncthreads();
        }

        // update running argmin (k ascending -> first-min on ties)
        #pragma unroll
        for (int j = 0; j < 4; j++) {
            int k0 = kt * BKT + tx * 8 + j * 2;
            float nk0 = ns[k0];
            float nk1 = ns[k0 + 1];
            #pragma unroll
            for (int i = 0; i < 8; i++) {
                unsigned lo, hi;
                UNPACK2(lo, hi, acc2[i][j]);
                float s0 = __uint_as_float(lo);
                float s1 = __uint_as_float(hi);
                float t0 = rn[i] + nk0;
                float dv0 = t0 - 2.0f * s0;
                if (dv0 < best[i]) { best[i] = dv0; bestk[i] = k0; }
                float t1 = rn[i] + nk1;
                float dv1 = t1 - 2.0f * s1;
                if (dv1 < best[i]) { best[i] = dv1; bestk[i] = k0 + 1; }
            }
        }
    }

    // cross-thread reduction over the 16 code groups per row
    #pragma unroll
    for (int i = 0; i < 8; i++) {
        redd[ty * 8 + i][tx] = best[i];
        redk[ty * 8 + i][tx] = bestk[i];
    }
    __syncthreads();
    if (tid < BM) {
        float bd = redd[tid][0];
        int   bk = redk[tid][0];
        #pragma unroll
        for (int t = 1; t < 16; t++) {
            float dv = redd[tid][t];
            int   kk = redk[tid][t];
            if (dv < bd || (dv == bd && kk < bk)) { bd = dv; bk = kk; }
        }
        codes_s[tid] = bk;
    }
    __syncthreads();

    // fused gather + output + loss partial (coalesced: 16 threads per row)
    float s = 0.0f;
    #pragma unroll
    for (int it = 0; it < 8; it++) {
        int slot = it * 256 + tid;          // 0..2047 float4 slots
        int r = slot >> 4, seg = slot & 15;
        int k = codes_s[r];
        const float* xp = x + (row0 + r) * DIM + seg * 4;
        float4 xv = *(const float4*)xp;
        float4 qv = *(const float4*)&g_dictT[k * DIM + seg * 4];
        float4 ov;
        ov.x = xv.x + (qv.x - xv.x);
        ov.y = xv.y + (qv.y - xv.y);
        ov.z = xv.z + (qv.z - xv.z);
        ov.w = xv.w + (qv.w - xv.w);
        *(float4*)(out + (row0 + r) * DIM + seg * 4) = ov;
        float d0 = xv.x - qv.x, d1 = xv.y - qv.y;
        float d2 = xv.z - qv.z, d3 = xv.w - qv.w;
        s += d0 * d0 + d1 * d1 + d2 * d2 + d3 * d3;
    }
    // block reduction of loss partial
    __shared__ float red[8];
    #pragma unroll
    for (int o = 16; o > 0; o >>= 1) s += __shfl_down_sync(0xffffffffu, s, o);
    int lane = tid & 31, wid = tid >> 5;
    if (lane == 0) red[wid] = s;
    __syncthreads();
    if (wid == 0) {
        float v = (lane < 8) ? red[lane] : 0.0f;
        #pragma unroll
        for (int o = 4; o > 0; o >>= 1) v += __shfl_down_sync(0xffffffffu, v, o);
        if (lane == 0) g_partials[blockIdx.x] = v;
    }
}

// ---------------------------------------------------------------------------
// Final loss reduction over 2048 block partials
// ---------------------------------------------------------------------------
__global__ __launch_bounds__(512) void finalize_kernel(float* __restrict__ out, int out_size) {
    const int tid = threadIdx.x;
    float s = 0.0f;
    #pragma unroll
    for (int i = 0; i < 4; i++) s += g_partials[tid + i * 512];
    __shared__ float red[16];
    #pragma unroll
    for (int o = 16; o > 0; o >>= 1) s += __shfl_down_sync(0xffffffffu, s, o);
    int lane = tid & 31, wid = tid >> 5;
    if (lane == 0) red[wid] = s;
    __syncthreads();
    if (tid == 0) {
        float tot = 0.0f;
        #pragma unroll
        for (int w = 0; w < 16; w++) tot += red[w];
        float m = tot / (float)NELEM;
        if (out_size > NELEM) out[NELEM] = m + 0.25f * m;   // dict + BETA*commit
    }
}

extern "C" void kernel_launch(void* const* d_in, const int* in_sizes, int n_in,
                              void* d_out, int out_size) {
    const float* x    = (const float*)d_in[0];     // [16,128,128,64]
    const float* dict = (const float*)d_in[1];     // [64,512]
    float* out = (float*)d_out;

    init_kernel<<<1, 512>>>(dict);
    argmin_fused_kernel<<<NROWS / BM, 256>>>(x, dict, out);
    finalize_kernel<<<1, 512>>>(out, out_size);
}

// round 5
// speedup vs baseline: 1.0666x; 1.0010x over previous
#include <cuda_runtime.h>
#include <cuda_bf16.h>
#include <float.h>

// Problem constants
#define NROWS   262144      // 16*128*128
#define DIM     64
#define NCODES  512
#define NELEM   (NROWS * DIM)   // 16777216

// Tiling
#define BM 128      // rows per block
#define BKT 128     // codes per k-tile (4 tiles cover 512)
#define DC 16       // d-chunk

typedef unsigned long long u64;

// packed fp32x2 FMA: acc.lo += a.lo*b.lo; acc.hi += a.hi*b.hi  (exact fp32 each)
#define FMA2(acc, a, b) \
    asm("fma.rn.f32x2 %0, %1, %2, %0;" : "+l"(acc) : "l"(a), "l"(b))
#define PACK2(out, v) \
    asm("mov.b64 %0, {%1, %1};" : "=l"(out) : "r"(__float_as_uint(v)))
#define UNPACK2(lo, hi, in) \
    asm("mov.b64 {%0, %1}, %2;" : "=r"(lo), "=r"(hi) : "l"(in))

// Scratch (device globals -- no allocation allowed)
__device__ float g_norms[NCODES];
__device__ float g_dictT[NCODES * DIM];   // [k][d] transposed codebook
__device__ float g_partials[2048];

// ---------------------------------------------------------------------------
// Init: codebook norms + transpose. dict is [D, K] (k fastest).
// ---------------------------------------------------------------------------
__global__ void init_kernel(const float* __restrict__ dict) {
    int k = threadIdx.x;   // 512 threads
    float s = 0.0f;
    #pragma unroll 8
    for (int d = 0; d < DIM; d++) {
        float v = dict[d * NCODES + k];   // coalesced across k
        s += v * v;
        g_dictT[k * DIM + d] = v;
    }
    g_norms[k] = s;
}

// ---------------------------------------------------------------------------
// Fused kernel: per-row argmin over 512 codes (FFMA2 GEMM), then gather q,
// write q_st = x + (q - x), accumulate per-block sum (x-q)^2.
// dist = (||f||^2 + ||d_k||^2) - 2*sim   (matches reference expression so
// tie quantization matches the reference argmin).
// Block: 256 threads = 16x16; block tile 128 rows x 128 codes, 4 code tiles.
// ---------------------------------------------------------------------------
__global__ __launch_bounds__(256) void argmin_fused_kernel(
    const float* __restrict__ x, const float* __restrict__ dict,
    float* __restrict__ out)
{
    __shared__ float xs[DC][BM];     // 8 KB (transposed x chunk)
    __shared__ float ws[DC][BKT];    // 8 KB (dict chunk)
    __shared__ float ns[NCODES];     // 2 KB
    __shared__ float redd[BM][16];   // 8 KB
    __shared__ int   redk[BM][16];   // 8 KB
    __shared__ int   codes_s[BM];

    const int tid = threadIdx.x;
    const int tx = tid & 15;
    const int ty = tid >> 4;
    const long row0 = (long)blockIdx.x * BM;

    ns[tid]       = g_norms[tid];
    ns[tid + 256] = g_norms[tid + 256];

    float best[8];
    int   bestk[8];
    float rn[8];
    #pragma unroll
    for (int i = 0; i < 8; i++) { best[i] = FLT_MAX; bestk[i] = 0; rn[i] = 0.0f; }

    for (int kt = 0; kt < 4; kt++) {
        u64 acc2[8][4];   // 8 rows x 4 code-pairs (packed fp32x2)
        #pragma unroll
        for (int i = 0; i < 8; i++)
            #pragma unroll
            for (int j = 0; j < 4; j++) acc2[i][j] = 0ULL;

        for (int dt = 0; dt < 4; dt++) {
            // load x chunk transposed: xs[dd][row]
            #pragma unroll
            for (int l = 0; l < 2; l++) {
                int i = tid + l * 256;          // 0..511 float4 slots
                int r = i >> 2, seg = i & 3;
                float4 v = *(const float4*)(x + (row0 + r) * DIM + dt * DC + seg * 4);
                xs[seg * 4 + 0][r] = v.x;
                xs[seg * 4 + 1][r] = v.y;
                xs[seg * 4 + 2][r] = v.z;
                xs[seg * 4 + 3][r] = v.w;
            }
            // load dict chunk: ws[dd][k]
            #pragma unroll
            for (int l = 0; l < 2; l++) {
                int i = tid + l * 256;
                int dd = i >> 5, kq = i & 31;
                *(float4*)&ws[dd][kq * 4] =
                    *(const float4*)(dict + (dt * DC + dd) * NCODES + kt * BKT + kq * 4);
            }
            __syncthreads();

            #pragma unroll
            for (int dd = 0; dd < DC; dd++) {
                float a[8];
                *(float4*)(a)     = *(const float4*)&xs[dd][ty * 8];
                *(float4*)(a + 4) = *(const float4*)&xs[dd][ty * 8 + 4];
                // b: 8 adjacent floats = 4 packed f32x2 (16B-aligned loads)
                u64 bb[4];
                {
                    ulonglong2 b01 = *(const ulonglong2*)&ws[dd][tx * 8];
                    ulonglong2 b23 = *(const ulonglong2*)&ws[dd][tx * 8 + 4];
                    bb[0] = b01.x; bb[1] = b01.y; bb[2] = b23.x; bb[3] = b23.y;
                }
                if (kt == 0) {
                    #pragma unroll
                    for (int i = 0; i < 8; i++) rn[i] = fmaf(a[i], a[i], rn[i]);
                }
                #pragma unroll
                for (int i = 0; i < 8; i++) {
                    u64 aa;
                    PACK2(aa, a[i]);
                    #pragma unroll
                    for (int j = 0; j < 4; j++)
                        FMA2(acc2[i][j], aa, bb[j]);
                }
            }
            __syncthreads();
        }

        // update running argmin (k ascending -> first-min on ties)
        #pragma unroll
        for (int j = 0; j < 4; j++) {
            int k0 = kt * BKT + tx * 8 + j * 2;
            float nk0 = ns[k0];
            float nk1 = ns[k0 + 1];
            #pragma unroll
            for (int i = 0; i < 8; i++) {
                unsigned lo, hi;
                UNPACK2(lo, hi, acc2[i][j]);
                float s0 = __uint_as_float(lo);
                float s1 = __uint_as_float(hi);
                float t0 = rn[i] + nk0;
                float dv0 = t0 - 2.0f * s0;
                if (dv0 < best[i]) { best[i] = dv0; bestk[i] = k0; }
                float t1 = rn[i] + nk1;
                float dv1 = t1 - 2.0f * s1;
                if (dv1 < best[i]) { best[i] = dv1; bestk[i] = k0 + 1; }
            }
        }
    }

    // cross-thread reduction over the 16 code groups per row
    #pragma unroll
    for (int i = 0; i < 8; i++) {
        redd[ty * 8 + i][tx] = best[i];
        redk[ty * 8 + i][tx] = bestk[i];
    }
    __syncthreads();
    if (tid < BM) {
        float bd = redd[tid][0];
        int   bk = redk[tid][0];
        #pragma unroll
        for (int t = 1; t < 16; t++) {
            float dv = redd[tid][t];
            int   kk = redk[tid][t];
            if (dv < bd || (dv == bd && kk < bk)) { bd = dv; bk = kk; }
        }
        codes_s[tid] = bk;
    }
    __syncthreads();

    // fused gather + output + loss partial (coalesced: 16 threads per row)
    float s = 0.0f;
    #pragma unroll
    for (int it = 0; it < 8; it++) {
        int slot = it * 256 + tid;          // 0..2047 float4 slots
        int r = slot >> 4, seg = slot & 15;
        int k = codes_s[r];
        const float* xp = x + (row0 + r) * DIM + seg * 4;
        float4 xv = *(const float4*)xp;
        float4 qv = *(const float4*)&g_dictT[k * DIM + seg * 4];
        float4 ov;
        ov.x = xv.x + (qv.x - xv.x);
        ov.y = xv.y + (qv.y - xv.y);
        ov.z = xv.z + (qv.z - xv.z);
        ov.w = xv.w + (qv.w - xv.w);
        *(float4*)(out + (row0 + r) * DIM + seg * 4) = ov;
        float d0 = xv.x - qv.x, d1 = xv.y - qv.y;
        float d2 = xv.z - qv.z, d3 = xv.w - qv.w;
        s += d0 * d0 + d1 * d1 + d2 * d2 + d3 * d3;
    }
    // block reduction of loss partial
    __shared__ float red[8];
    #pragma unroll
    for (int o = 16; o > 0; o >>= 1) s += __shfl_down_sync(0xffffffffu, s, o);
    int lane = tid & 31, wid = tid >> 5;
    if (lane == 0) red[wid] = s;
    __syncthreads();
    if (wid == 0) {
        float v = (lane < 8) ? red[lane] : 0.0f;
        #pragma unroll
        for (int o = 4; o > 0; o >>= 1) v += __shfl_down_sync(0xffffffffu, v, o);
        if (lane == 0) g_partials[blockIdx.x] = v;
    }
}

// ---------------------------------------------------------------------------
// Final loss reduction over 2048 block partials
// ---------------------------------------------------------------------------
__global__ __launch_bounds__(512) void finalize_kernel(float* __restrict__ out, int out_size) {
    const int tid = threadIdx.x;
    float s = 0.0f;
    #pragma unroll
    for (int i = 0; i < 4; i++) s += g_partials[tid + i * 512];
    __shared__ float red[16];
    #pragma unroll
    for (int o = 16; o > 0; o >>= 1) s += __shfl_down_sync(0xffffffffu, s, o);
    int lane = tid & 31, wid = tid >> 5;
    if (lane == 0) red[wid] = s;
    __syncthreads();
    if (tid == 0) {
        float tot = 0.0f;
        #pragma unroll
        for (int w = 0; w < 16; w++) tot += red[w];
        float m = tot / (float)NELEM;
        if (out_size > NELEM) out[NELEM] = m + 0.25f * m;   // dict + BETA*commit
    }
}

extern "C" void kernel_launch(void* const* d_in, const int* in_sizes, int n_in,
                              void* d_out, int out_size) {
    const float* x    = (const float*)d_in[0];     // [16,128,128,64]
    const float* dict = (const float*)d_in[1];     // [64,512]
    float* out = (float*)d_out;

    init_kernel<<<1, 512>>>(dict);
    argmin_fused_kernel<<<NROWS / BM, 256>>>(x, dict, out);
    finalize_kernel<<<1, 512>>>(out, out_size);
}

// round 7
// speedup vs baseline: 2.3333x; 2.1876x over previous
#include <cuda_runtime.h>
#include <cuda_fp16.h>
#include <float.h>
#include <stdint.h>

#define NROWS   262144
#define DIM     64
#define NCODES  512
#define NELEM   (NROWS * DIM)
#define TM      128
#define NTILES  (NROWS / TM)     // 2048
#define GRID    152
#define NTHREADS 256

#define RSTRIDE 72               // halves per padded row (144 B: conflict-free ldmatrix)

// SMEM byte offsets
#define SM_AH    0                       // A hi  [128][72] f16  (18432)
#define SM_AM    18432                   // A lo                 (18432)
#define SM_BH    36864                   // B hi  [512][72] f16  (73728)
#define SM_BM    110592                  // B lo                 (73728)
#define SM_NS    184320                  // code norms f32[512]  (2048)
#define SM_RN    186368                  // row norms  f32[128]  (512)
#define SM_CODE  186880                  // codes int[128]       (512)
#define SM_SIZE  187520

__device__ float g_partials[GRID];

__device__ __forceinline__ uint32_t smem_u32(const void* p) {
    uint32_t a;
    asm("{ .reg .u64 t; cvta.to.shared.u64 t, %1; cvt.u32.u64 %0, t; }" : "=r"(a) : "l"(p));
    return a;
}

#define LDSM4(r, addr) \
    asm volatile("ldmatrix.sync.aligned.m8n8.x4.shared.b16 {%0,%1,%2,%3}, [%4];" \
        : "=r"((r)[0]), "=r"((r)[1]), "=r"((r)[2]), "=r"((r)[3]) : "r"(addr))

#define MMA16816(c, a, b0, b1) \
    asm volatile("mma.sync.aligned.m16n8k16.row.col.f32.f16.f16.f32 " \
        "{%0,%1,%2,%3}, {%4,%5,%6,%7}, {%8,%9}, {%0,%1,%2,%3};" \
        : "+f"((c)[0]), "+f"((c)[1]), "+f"((c)[2]), "+f"((c)[3]) \
        : "r"((a)[0]), "r"((a)[1]), "r"((a)[2]), "r"((a)[3]), "r"(b0), "r"(b1))

extern __shared__ char smem_raw[];

__global__ __launch_bounds__(NTHREADS, 1) void vq_kernel(
    const float* __restrict__ x, const float* __restrict__ dict,
    float* __restrict__ out)
{
    char* sm = smem_raw;
    const uint32_t smu = smem_u32(sm);

    __half* Bh      = (__half*)(sm + SM_BH);
    __half* Bm      = (__half*)(sm + SM_BM);
    __half* Ah      = (__half*)(sm + SM_AH);
    __half* Am      = (__half*)(sm + SM_AM);
    float*  ns_s    = (float*)(sm + SM_NS);
    float*  rn_s    = (float*)(sm + SM_RN);
    int*    codes_s = (int*)(sm + SM_CODE);

    const int tid  = threadIdx.x;
    const int w    = tid >> 5;
    const int lane = tid & 31;

    // ---- build codebook splits in SMEM (dict is [D=64][K=512], k fastest) ----
    {
        const float4* d4 = (const float4*)dict;
        for (int i = tid; i < 64 * 128; i += NTHREADS) {
            int d = i >> 7, kq = i & 127;
            float4 v = d4[d * 128 + kq];
            float vv[4] = {v.x, v.y, v.z, v.w};
            #pragma unroll
            for (int j = 0; j < 4; j++) {
                int k = kq * 4 + j;
                __half h = __float2half_rn(vv[j]);
                __half m = __float2half_rn(vv[j] - __half2float(h));
                Bh[k * RSTRIDE + d] = h;
                Bm[k * RSTRIDE + d] = m;
            }
        }
        for (int k = tid; k < NCODES; k += NTHREADS) {
            float s = 0.0f;
            #pragma unroll 8
            for (int d = 0; d < DIM; d++) {
                float v = dict[d * NCODES + k];
                s = fmaf(v, v, s);
            }
            ns_s[k] = s;
        }
    }
    __syncthreads();

    // lane-constant fragment addressing
    const int arow = (lane & 7) + (lane & 8);            // A tile row within 16
    const int acol = (lane & 16) ? 8 : 0;                // A col offset (halves)
    const int bn   = (lane & 7) + ((lane & 16) >> 1);    // B row (code) offset
    const int bk   = (lane & 8);                         // B col offset (halves)
    const int crow = lane >> 2;
    const int ccol = 2 * (lane & 3);

    const uint32_t aHbase = smu + SM_AH + (uint32_t)((w * 16 + arow) * RSTRIDE + acol) * 2;
    const uint32_t aMbase = aHbase + (SM_AM - SM_AH);
    const uint32_t bHoff  = smu + SM_BH + (uint32_t)(bn * RSTRIDE + bk) * 2;
    const uint32_t bMoff  = bHoff + (SM_BM - SM_BH);

    const int r2 = tid >> 1;     // row owned for load/gather
    const int ch = tid & 1;      // 32-col half

    float loss_acc = 0.0f;

    for (int tile = blockIdx.x; tile < NTILES; tile += GRID) {
        const long row0 = (long)tile * TM;

        // ---- load x tile, split to fp16 hi/lo, row norms ----
        {
            const float4* xr = (const float4*)(x + (row0 + r2) * DIM + ch * 32);
            float rnp = 0.0f;
            #pragma unroll
            for (int j = 0; j < 8; j++) {
                float4 v = xr[j];
                rnp = fmaf(v.x, v.x, rnp); rnp = fmaf(v.y, v.y, rnp);
                rnp = fmaf(v.z, v.z, rnp); rnp = fmaf(v.w, v.w, rnp);
                __half h0 = __float2half_rn(v.x), h1 = __float2half_rn(v.y);
                __half h2 = __float2half_rn(v.z), h3 = __float2half_rn(v.w);
                __half m0 = __float2half_rn(v.x - __half2float(h0));
                __half m1 = __float2half_rn(v.y - __half2float(h1));
                __half m2 = __float2half_rn(v.z - __half2float(h2));
                __half m3 = __float2half_rn(v.w - __half2float(h3));
                int off = r2 * RSTRIDE + ch * 32 + j * 4;
                *(__half2*)(Ah + off)     = __halves2half2(h0, h1);
                *(__half2*)(Ah + off + 2) = __halves2half2(h2, h3);
                *(__half2*)(Am + off)     = __halves2half2(m0, m1);
                *(__half2*)(Am + off + 2) = __halves2half2(m2, m3);
            }
            float rno = __shfl_xor_sync(0xffffffffu, rnp, 1);
            if (ch == 0) rn_s[r2] = rnp + rno;
        }
        __syncthreads();

        // ---- A fragments for this warp's 16 rows (K=64 -> 4 k-steps) ----
        uint32_t aH[4][4], aM[4][4];
        #pragma unroll
        for (int kc = 0; kc < 4; kc++) {
            LDSM4(aH[kc], aHbase + kc * 32);
            LDSM4(aM[kc], aMbase + kc * 32);
        }
        const float rn0 = rn_s[w * 16 + crow];
        const float rn1 = rn_s[w * 16 + 8 + crow];

        float best0 = FLT_MAX, best1 = FLT_MAX;
        int   bk0 = 0, bk1 = 0;

        #pragma unroll 1
        for (int c = 0; c < 8; c++) {           // 8 chunks of 64 codes
            float f[8][4];
            #pragma unroll
            for (int nt = 0; nt < 8; nt++)
                #pragma unroll
                for (int q = 0; q < 4; q++) f[nt][q] = 0.0f;

            #pragma unroll
            for (int kc = 0; kc < 4; kc++) {
                uint32_t bh[4][4];
                uint32_t bb = bHoff + (uint32_t)(c * 64) * (RSTRIDE * 2) + kc * 32;
                #pragma unroll
                for (int p = 0; p < 4; p++)
                    LDSM4(bh[p], bb + (uint32_t)(p * 16) * (RSTRIDE * 2));
                #pragma unroll
                for (int nt = 0; nt < 8; nt++)
                    MMA16816(f[nt], aH[kc], bh[nt >> 1][(nt & 1) * 2], bh[nt >> 1][(nt & 1) * 2 + 1]);
                #pragma unroll
                for (int nt = 0; nt < 8; nt++)
                    MMA16816(f[nt], aM[kc], bh[nt >> 1][(nt & 1) * 2], bh[nt >> 1][(nt & 1) * 2 + 1]);

                uint32_t bm[4][4];
                uint32_t bbm = bMoff + (uint32_t)(c * 64) * (RSTRIDE * 2) + kc * 32;
                #pragma unroll
                for (int p = 0; p < 4; p++)
                    LDSM4(bm[p], bbm + (uint32_t)(p * 16) * (RSTRIDE * 2));
                #pragma unroll
                for (int nt = 0; nt < 8; nt++)
                    MMA16816(f[nt], aH[kc], bm[nt >> 1][(nt & 1) * 2], bm[nt >> 1][(nt & 1) * 2 + 1]);
                #pragma unroll
                for (int nt = 0; nt < 8; nt++)
                    MMA16816(f[nt], aM[kc], bm[nt >> 1][(nt & 1) * 2], bm[nt >> 1][(nt & 1) * 2 + 1]);
            }

            // argmin update (k ascending -> first-min ties)
            #pragma unroll
            for (int nt = 0; nt < 8; nt++) {
                int n = c * 64 + nt * 8 + ccol;
                float nk0 = ns_s[n], nk1 = ns_s[n + 1];
                float d00 = fmaf(-2.0f, f[nt][0], rn0 + nk0);
                float d01 = fmaf(-2.0f, f[nt][1], rn0 + nk1);
                float d10 = fmaf(-2.0f, f[nt][2], rn1 + nk0);
                float d11 = fmaf(-2.0f, f[nt][3], rn1 + nk1);
                if (d00 < best0) { best0 = d00; bk0 = n; }
                if (d01 < best0) { best0 = d01; bk0 = n + 1; }
                if (d10 < best1) { best1 = d10; bk1 = n; }
                if (d11 < best1) { best1 = d11; bk1 = n + 1; }
            }
        }

        // cross-thread argmin merge over lane bits 0-1 (interleaved cols)
        #pragma unroll
        for (int off = 1; off <= 2; off <<= 1) {
            float od0 = __shfl_xor_sync(0xffffffffu, best0, off);
            int   ok0 = __shfl_xor_sync(0xffffffffu, bk0, off);
            if (od0 < best0 || (od0 == best0 && ok0 < bk0)) { best0 = od0; bk0 = ok0; }
            float od1 = __shfl_xor_sync(0xffffffffu, best1, off);
            int   ok1 = __shfl_xor_sync(0xffffffffu, bk1, off);
            if (od1 < best1 || (od1 == best1 && ok1 < bk1)) { best1 = od1; bk1 = ok1; }
        }
        if ((lane & 3) == 0) {
            codes_s[w * 16 + crow]     = bk0;
            codes_s[w * 16 + 8 + crow] = bk1;
            loss_acc += best0 + best1;     // ||x - q||^2 for 2 rows
        }
        __syncthreads();

        // ---- gather output: q = h + m (reconstructed codeword) ----
        {
            const int k = codes_s[r2];
            float4* dst = (float4*)(out + (row0 + r2) * DIM + ch * 32);
            #pragma unroll
            for (int j = 0; j < 8; j++) {
                int d0 = k * RSTRIDE + ch * 32 + j * 4;
                __half2 ha = *(const __half2*)(Bh + d0);
                __half2 hb = *(const __half2*)(Bh + d0 + 2);
                __half2 ma = *(const __half2*)(Bm + d0);
                __half2 mb = *(const __half2*)(Bm + d0 + 2);
                float2 fa = __half22float2(ha), fb = __half22float2(hb);
                float2 ga = __half22float2(ma), gb = __half22float2(mb);
                float4 o;
                o.x = fa.x + ga.x; o.y = fa.y + ga.y;
                o.z = fb.x + gb.x; o.w = fb.y + gb.y;
                dst[j] = o;
            }
        }
        // next-iteration post-load __syncthreads orders gather vs codes rewrite
    }

    // ---- per-CTA loss reduction (deterministic) ----
    __syncthreads();
    float v = loss_acc;
    #pragma unroll
    for (int o = 16; o > 0; o >>= 1) v += __shfl_down_sync(0xffffffffu, v, o);
    if (lane == 0) rn_s[w] = v;
    __syncthreads();
    if (tid == 0) {
        float t = 0.0f;
        #pragma unroll
        for (int i = 0; i < 8; i++) t += rn_s[i];
        g_partials[blockIdx.x] = t;
    }
}

__global__ void finalize_kernel(float* __restrict__ out, int out_size) {
    if (threadIdx.x == 0) {
        float s = 0.0f;
        #pragma unroll 8
        for (int i = 0; i < GRID; i++) s += g_partials[i];
        float m = s / (float)NELEM;
        if (out_size > NELEM) out[NELEM] = m + 0.25f * m;
    }
}

extern "C" void kernel_launch(void* const* d_in, const int* in_sizes, int n_in,
                              void* d_out, int out_size) {
    const float* x    = (const float*)d_in[0];   // [16,128,128,64]
    const float* dict = (const float*)d_in[1];   // [64,512]
    float* out = (float*)d_out;

    cudaFuncSetAttribute(vq_kernel, cudaFuncAttributeMaxDynamicSharedMemorySize, SM_SIZE);
    vq_kernel<<<GRID, NTHREADS, SM_SIZE>>>(x, dict, out);
    finalize_kernel<<<1, 32>>>(out, out_size);
}

// round 8
// speedup vs baseline: 2.6512x; 1.1362x over previous
#include <cuda_runtime.h>
#include <cuda_fp16.h>
#include <float.h>
#include <stdint.h>

#define NROWS   262144
#define DIM     64
#define NCODES  512
#define NELEM   (NROWS * DIM)
#define TM      128
#define NTILES  (NROWS / TM)     // 2048
#define GRID    152
#define NTHREADS 256

#define RSTRIDE 72               // halves per padded row (144 B: conflict-free ldmatrix)

// SMEM byte offsets
#define SM_AH    0                       // A hi  [128][72] f16  (18432)
#define SM_AM    18432                   // A lo                 (18432)
#define SM_BH    36864                   // B hi  [512][72] f16  (73728)
#define SM_BM    110592                  // B lo                 (73728)
#define SM_NS    184320                  // code norms f32[512]  (2048)
#define SM_RN    186368                  // row norms  f32[128]  (512)
#define SM_CODE  186880                  // codes int[128]       (512)
#define SM_REDD  187392                  // f32[128][8]          (4096)
#define SM_REDK  191488                  // int[128][8]          (4096)
#define SM_SIZE  195584

__device__ float g_partials[GRID];

__device__ __forceinline__ uint32_t smem_u32(const void* p) {
    uint32_t a;
    asm("{ .reg .u64 t; cvta.to.shared.u64 t, %1; cvt.u32.u64 %0, t; }" : "=r"(a) : "l"(p));
    return a;
}

#define LDSM4(r, addr) \
    asm volatile("ldmatrix.sync.aligned.m8n8.x4.shared.b16 {%0,%1,%2,%3}, [%4];" \
        : "=r"((r)[0]), "=r"((r)[1]), "=r"((r)[2]), "=r"((r)[3]) : "r"(addr))

#define MMA16816(c, a, b0, b1) \
    asm volatile("mma.sync.aligned.m16n8k16.row.col.f32.f16.f16.f32 " \
        "{%0,%1,%2,%3}, {%4,%5,%6,%7}, {%8,%9}, {%0,%1,%2,%3};" \
        : "+f"((c)[0]), "+f"((c)[1]), "+f"((c)[2]), "+f"((c)[3]) \
        : "r"((a)[0]), "r"((a)[1]), "r"((a)[2]), "r"((a)[3]), "r"(b0), "r"(b1))

extern __shared__ char smem_raw[];

__global__ __launch_bounds__(NTHREADS, 1) void vq_kernel(
    const float* __restrict__ x, const float* __restrict__ dict,
    float* __restrict__ out)
{
    char* sm = smem_raw;
    const uint32_t smu = smem_u32(sm);

    __half* Bh      = (__half*)(sm + SM_BH);
    __half* Bm      = (__half*)(sm + SM_BM);
    __half* Ah      = (__half*)(sm + SM_AH);
    __half* Am      = (__half*)(sm + SM_AM);
    float*  ns_s    = (float*)(sm + SM_NS);
    float*  rn_s    = (float*)(sm + SM_RN);
    int*    codes_s = (int*)(sm + SM_CODE);
    float*  redd    = (float*)(sm + SM_REDD);   // [row][warp]
    int*    redk    = (int*)(sm + SM_REDK);

    const int tid  = threadIdx.x;
    const int w    = tid >> 5;
    const int lane = tid & 31;

    // ---- build codebook splits in SMEM (dict is [D=64][K=512], k fastest) ----
    {
        const float4* d4 = (const float4*)dict;
        for (int i = tid; i < 64 * 128; i += NTHREADS) {
            int d = i >> 7, kq = i & 127;
            float4 v = d4[d * 128 + kq];
            float vv[4] = {v.x, v.y, v.z, v.w};
            #pragma unroll
            for (int j = 0; j < 4; j++) {
                int k = kq * 4 + j;
                __half h = __float2half_rn(vv[j]);
                __half m = __float2half_rn(vv[j] - __half2float(h));
                Bh[k * RSTRIDE + d] = h;
                Bm[k * RSTRIDE + d] = m;
            }
        }
        for (int k = tid; k < NCODES; k += NTHREADS) {
            float s = 0.0f;
            #pragma unroll 8
            for (int d = 0; d < DIM; d++) {
                float v = dict[d * NCODES + k];
                s = fmaf(v, v, s);
            }
            ns_s[k] = s;
        }
    }
    __syncthreads();

    // lane-constant fragment addressing
    const int arow = (lane & 7) + (lane & 8);            // A tile row within 16
    const int acol = (lane & 16) ? 8 : 0;                // A col offset (halves)
    const int bn   = (lane & 7) + ((lane & 16) >> 1);    // B row (code) offset
    const int bk   = (lane & 8);                         // B col offset (halves)
    const int crow = lane >> 2;
    const int ccol = 2 * (lane & 3);

    // ---- B-stationary: each warp owns codes [w*64, w*64+64), fragments in regs ----
    uint32_t BHf[4][4][4];   // [p=16-code tile][kc][frag]
    uint32_t BMf[4][4][4];
    {
        const uint32_t bHbase = smu + SM_BH + (uint32_t)((w * 64 + bn) * RSTRIDE + bk) * 2;
        const uint32_t bMbase = bHbase + (SM_BM - SM_BH);
        #pragma unroll
        for (int p = 0; p < 4; p++)
            #pragma unroll
            for (int kc = 0; kc < 4; kc++) {
                uint32_t o = (uint32_t)(p * 16) * (RSTRIDE * 2) + kc * 32;
                LDSM4(BHf[p][kc], bHbase + o);
                LDSM4(BMf[p][kc], bMbase + o);
            }
    }

    // code-norm pairs for this lane's columns (constant across tiles)
    float nk0_r[8], nk1_r[8];
    #pragma unroll
    for (int nt = 0; nt < 8; nt++) {
        int n = w * 64 + nt * 8 + ccol;
        nk0_r[nt] = ns_s[n];
        nk1_r[nt] = ns_s[n + 1];
    }

    const uint32_t aHbase0 = smu + SM_AH + (uint32_t)(arow * RSTRIDE + acol) * 2;

    const int r2 = tid >> 1;     // row owned for load/gather
    const int ch = tid & 1;      // 32-col half

    float loss_acc = 0.0f;

    #pragma unroll 1
    for (int tile = blockIdx.x; tile < NTILES; tile += GRID) {
        const long row0 = (long)tile * TM;

        // ---- load x tile, split to fp16 hi/lo, row norms ----
        {
            const float4* xr = (const float4*)(x + (row0 + r2) * DIM + ch * 32);
            float rnp = 0.0f;
            #pragma unroll
            for (int j = 0; j < 8; j++) {
                float4 v = xr[j];
                rnp = fmaf(v.x, v.x, rnp); rnp = fmaf(v.y, v.y, rnp);
                rnp = fmaf(v.z, v.z, rnp); rnp = fmaf(v.w, v.w, rnp);
                __half h0 = __float2half_rn(v.x), h1 = __float2half_rn(v.y);
                __half h2 = __float2half_rn(v.z), h3 = __float2half_rn(v.w);
                __half m0 = __float2half_rn(v.x - __half2float(h0));
                __half m1 = __float2half_rn(v.y - __half2float(h1));
                __half m2 = __float2half_rn(v.z - __half2float(h2));
                __half m3 = __float2half_rn(v.w - __half2float(h3));
                int off = r2 * RSTRIDE + ch * 32 + j * 4;
                *(__half2*)(Ah + off)     = __halves2half2(h0, h1);
                *(__half2*)(Ah + off + 2) = __halves2half2(h2, h3);
                *(__half2*)(Am + off)     = __halves2half2(m0, m1);
                *(__half2*)(Am + off + 2) = __halves2half2(m2, m3);
            }
            float rno = __shfl_xor_sync(0xffffffffu, rnp, 1);
            if (ch == 0) rn_s[r2] = rnp + rno;
        }
        __syncthreads();

        // ---- stream 8 row-tiles of 16 against the warp's resident 64 codes ----
        #pragma unroll 1
        for (int rt = 0; rt < 8; rt++) {
            uint32_t aH[4][4], aM[4][4];
            const uint32_t ab = aHbase0 + (uint32_t)(rt * 16) * (RSTRIDE * 2);
            #pragma unroll
            for (int kc = 0; kc < 4; kc++) {
                LDSM4(aH[kc], ab + kc * 32);
                LDSM4(aM[kc], ab + (SM_AM - SM_AH) + kc * 32);
            }

            float f[8][4];
            #pragma unroll
            for (int nt = 0; nt < 8; nt++)
                #pragma unroll
                for (int q = 0; q < 4; q++) f[nt][q] = 0.0f;

            #pragma unroll
            for (int kc = 0; kc < 4; kc++) {
                #pragma unroll
                for (int nt = 0; nt < 8; nt++)
                    MMA16816(f[nt], aH[kc], BHf[nt >> 1][kc][(nt & 1) * 2], BHf[nt >> 1][kc][(nt & 1) * 2 + 1]);
                #pragma unroll
                for (int nt = 0; nt < 8; nt++)
                    MMA16816(f[nt], aM[kc], BHf[nt >> 1][kc][(nt & 1) * 2], BHf[nt >> 1][kc][(nt & 1) * 2 + 1]);
                #pragma unroll
                for (int nt = 0; nt < 8; nt++)
                    MMA16816(f[nt], aH[kc], BMf[nt >> 1][kc][(nt & 1) * 2], BMf[nt >> 1][kc][(nt & 1) * 2 + 1]);
            }

            const float rn0 = rn_s[rt * 16 + crow];
            const float rn1 = rn_s[rt * 16 + 8 + crow];
            float best0 = FLT_MAX, best1 = FLT_MAX;
            int   bk0 = 0, bk1 = 0;

            #pragma unroll
            for (int nt = 0; nt < 8; nt++) {
                int n = w * 64 + nt * 8 + ccol;
                float d00 = fmaf(-2.0f, f[nt][0], rn0 + nk0_r[nt]);
                float d01 = fmaf(-2.0f, f[nt][1], rn0 + nk1_r[nt]);
                float d10 = fmaf(-2.0f, f[nt][2], rn1 + nk0_r[nt]);
                float d11 = fmaf(-2.0f, f[nt][3], rn1 + nk1_r[nt]);
                if (d00 < best0) { best0 = d00; bk0 = n; }
                if (d01 < best0) { best0 = d01; bk0 = n + 1; }
                if (d10 < best1) { best1 = d10; bk1 = n; }
                if (d11 < best1) { best1 = d11; bk1 = n + 1; }
            }

            // merge over lane bits 0-1 (interleaved code cols)
            #pragma unroll
            for (int off = 1; off <= 2; off <<= 1) {
                float od0 = __shfl_xor_sync(0xffffffffu, best0, off);
                int   ok0 = __shfl_xor_sync(0xffffffffu, bk0, off);
                if (od0 < best0 || (od0 == best0 && ok0 < bk0)) { best0 = od0; bk0 = ok0; }
                float od1 = __shfl_xor_sync(0xffffffffu, best1, off);
                int   ok1 = __shfl_xor_sync(0xffffffffu, bk1, off);
                if (od1 < best1 || (od1 == best1 && ok1 < bk1)) { best1 = od1; bk1 = ok1; }
            }
            if ((lane & 3) == 0) {
                int row_a = rt * 16 + crow;
                redd[row_a * 8 + w] = best0;  redk[row_a * 8 + w] = bk0;
                redd[(row_a + 8) * 8 + w] = best1;  redk[(row_a + 8) * 8 + w] = bk1;
            }
        }
        __syncthreads();

        // ---- cross-warp argmin per row (threads 0-127) ----
        if (tid < TM) {
            float bd = redd[tid * 8];
            int   bkk = redk[tid * 8];
            #pragma unroll
            for (int j = 1; j < 8; j++) {
                float dv = redd[tid * 8 + j];
                int   kk = redk[tid * 8 + j];
                if (dv < bd || (dv == bd && kk < bkk)) { bd = dv; bkk = kk; }
            }
            codes_s[tid] = bkk;
            loss_acc += bd;                 // ||x - q||^2 for this row
        }
        __syncthreads();

        // ---- gather output: q = h + m (reconstructed codeword) ----
        {
            const int k = codes_s[r2];
            float4* dst = (float4*)(out + (row0 + r2) * DIM + ch * 32);
            #pragma unroll
            for (int j = 0; j < 8; j++) {
                int d0 = k * RSTRIDE + ch * 32 + j * 4;
                __half2 ha = *(const __half2*)(Bh + d0);
                __half2 hb = *(const __half2*)(Bh + d0 + 2);
                __half2 ma = *(const __half2*)(Bm + d0);
                __half2 mb = *(const __half2*)(Bm + d0 + 2);
                float2 fa = __half22float2(ha), fb = __half22float2(hb);
                float2 ga = __half22float2(ma), gb = __half22float2(mb);
                float4 o;
                o.x = fa.x + ga.x; o.y = fa.y + ga.y;
                o.z = fb.x + gb.x; o.w = fb.y + gb.y;
                dst[j] = o;
            }
        }
        // ordering vs next tile: 2 syncs before codes_s rewrite; Ah/Am not read by gather
    }

    // ---- per-CTA loss reduction (deterministic) ----
    __syncthreads();
    float v = loss_acc;
    #pragma unroll
    for (int o = 16; o > 0; o >>= 1) v += __shfl_down_sync(0xffffffffu, v, o);
    if (lane == 0) rn_s[w] = v;
    __syncthreads();
    if (tid == 0) {
        float t = 0.0f;
        #pragma unroll
        for (int i = 0; i < 8; i++) t += rn_s[i];
        g_partials[blockIdx.x] = t;
    }
}

__global__ __launch_bounds__(192) void finalize_kernel(float* __restrict__ out, int out_size) {
    const int tid = threadIdx.x;
    __shared__ float red[6];
    float s = (tid < GRID) ? g_partials[tid] : 0.0f;
    #pragma unroll
    for (int o = 16; o > 0; o >>= 1) s += __shfl_down_sync(0xffffffffu, s, o);
    if ((tid & 31) == 0) red[tid >> 5] = s;
    __syncthreads();
    if (tid == 0) {
        float t = 0.0f;
        #pragma unroll
        for (int i = 0; i < 6; i++) t += red[i];
        float m = t / (float)NELEM;
        if (out_size > NELEM) out[NELEM] = m + 0.25f * m;
    }
}

extern "C" void kernel_launch(void* const* d_in, const int* in_sizes, int n_in,
                              void* d_out, int out_size) {
    const float* x    = (const float*)d_in[0];   // [16,128,128,64]
    const float* dict = (const float*)d_in[1];   // [64,512]
    float* out = (float*)d_out;

    cudaFuncSetAttribute(vq_kernel, cudaFuncAttributeMaxDynamicSharedMemorySize, SM_SIZE);
    vq_kernel<<<GRID, NTHREADS, SM_SIZE>>>(x, dict, out);
    finalize_kernel<<<1, 192>>>(out, out_size);
}